// round 5
// baseline (speedup 1.0000x reference)
#include <cuda_runtime.h>
#include <cuda_bf16.h>
#include <math.h>
#include <stdint.h>

#define B_ 64
#define T_ 512
#define D_ 1024
#define H_ 1024
#define G_ 4096

// ---------------- device scratch (allocation-free rule) ----------------
__device__ float g_xg[(size_t)T_ * B_ * G_];            // [T][B][4H] pre-activations
__device__ float g_c[B_ * H_];                          // cell state
__device__ __nv_bfloat16 g_hh[2][128 * H_];             // ping-pong; rows 0-63 h_hi, 64-127 h_lo
__device__ __nv_bfloat16 g_WW[(size_t)G_ * 2 * H_];     // [4096][2048]: 0-1023 W_hi, 1024-2047 W_lo
__device__ int g_flags[128];                            // grid barrier flags

#define SWZ(off) ((off) ^ (((off) >> 3) & 0x70))

__device__ __forceinline__ uint32_t smem_to_u32(const void* p) {
    uint32_t a;
    asm("{ .reg .u64 t; cvta.to.shared.u64 t, %1; cvt.u32.u64 %0, t; }" : "=r"(a) : "l"(p));
    return a;
}

__device__ __forceinline__ void ldsm_x4(uint32_t& r0, uint32_t& r1, uint32_t& r2,
                                        uint32_t& r3, uint32_t addr) {
    asm volatile("ldmatrix.sync.aligned.m8n8.x4.shared.b16 {%0,%1,%2,%3}, [%4];"
                 : "=r"(r0), "=r"(r1), "=r"(r2), "=r"(r3) : "r"(addr));
}

__device__ __forceinline__ void hmma16816(float* d, uint32_t a0, uint32_t a1,
                                          uint32_t a2, uint32_t a3,
                                          uint32_t b0, uint32_t b1) {
    asm volatile(
        "mma.sync.aligned.m16n8k16.row.col.f32.bf16.bf16.f32 "
        "{%0,%1,%2,%3}, {%4,%5,%6,%7}, {%8,%9}, {%0,%1,%2,%3};"
        : "+f"(d[0]), "+f"(d[1]), "+f"(d[2]), "+f"(d[3])
        : "r"(a0), "r"(a1), "r"(a2), "r"(a3), "r"(b0), "r"(b1));
}

// ---------------- init kernels ----------------
__global__ void init_state_kernel() {
    int i = blockIdx.x * blockDim.x + threadIdx.x;
    if (i < B_ * H_) g_c[i] = 0.f;
    if (i < 128 * H_) {
        g_hh[0][i] = __float2bfloat16(0.f);
        g_hh[1][i] = __float2bfloat16(0.f);
    }
    if (i < 128) g_flags[i] = 0;
}

__global__ void build_WW_kernel(const float* __restrict__ W_hh) {
    int i = blockIdx.x * blockDim.x + threadIdx.x;
    if (i < G_ * H_) {
        int row = i >> 10, col = i & 1023;
        float w = W_hh[i];
        __nv_bfloat16 hi = __float2bfloat16(w);
        __nv_bfloat16 lo = __float2bfloat16(w - __bfloat162float(hi));
        g_WW[(size_t)row * 2048 + col] = hi;
        g_WW[(size_t)row * 2048 + 1024 + col] = lo;
    }
}

// ---------------- Phase A: x_gates GEMM (fp32, proven) ----------------
__global__ __launch_bounds__(256) void gemm_xg_kernel(
    const float* __restrict__ feature, const float* __restrict__ W_ih,
    const float* __restrict__ b_ih, const float* __restrict__ b_hh)
{
    __shared__ __align__(16) float As[16][68];
    __shared__ __align__(16) float Bs[16][68];
    int tid = threadIdx.x;
    int tx = tid & 15, ty = tid >> 4;
    int n0 = blockIdx.x * 64;
    int t  = blockIdx.y;
    int lr = tid >> 2;
    int lk = (tid & 3) * 4;

    const float* fptr = feature + ((size_t)lr * T_ + t) * D_ + lk;
    const float* wptr = W_ih + (size_t)(n0 + lr) * D_ + lk;

    float acc[4][4] = {};
    for (int k0 = 0; k0 < D_; k0 += 16) {
        float4 av = *(const float4*)(fptr + k0);
        float4 bv = *(const float4*)(wptr + k0);
        __syncthreads();
        As[lk + 0][lr] = av.x; As[lk + 1][lr] = av.y;
        As[lk + 2][lr] = av.z; As[lk + 3][lr] = av.w;
        Bs[lk + 0][lr] = bv.x; Bs[lk + 1][lr] = bv.y;
        Bs[lk + 2][lr] = bv.z; Bs[lk + 3][lr] = bv.w;
        __syncthreads();
#pragma unroll
        for (int k = 0; k < 16; k++) {
            float4 a4 = *(const float4*)&As[k][ty * 4];
            float4 b4 = *(const float4*)&Bs[k][tx * 4];
            acc[0][0] = fmaf(a4.x, b4.x, acc[0][0]);
            acc[0][1] = fmaf(a4.x, b4.y, acc[0][1]);
            acc[0][2] = fmaf(a4.x, b4.z, acc[0][2]);
            acc[0][3] = fmaf(a4.x, b4.w, acc[0][3]);
            acc[1][0] = fmaf(a4.y, b4.x, acc[1][0]);
            acc[1][1] = fmaf(a4.y, b4.y, acc[1][1]);
            acc[1][2] = fmaf(a4.y, b4.z, acc[1][2]);
            acc[1][3] = fmaf(a4.y, b4.w, acc[1][3]);
            acc[2][0] = fmaf(a4.z, b4.x, acc[2][0]);
            acc[2][1] = fmaf(a4.z, b4.y, acc[2][1]);
            acc[2][2] = fmaf(a4.z, b4.z, acc[2][2]);
            acc[2][3] = fmaf(a4.z, b4.w, acc[2][3]);
            acc[3][0] = fmaf(a4.w, b4.x, acc[3][0]);
            acc[3][1] = fmaf(a4.w, b4.y, acc[3][1]);
            acc[3][2] = fmaf(a4.w, b4.z, acc[3][2]);
            acc[3][3] = fmaf(a4.w, b4.w, acc[3][3]);
        }
    }
    int n = n0 + tx * 4;
    float bx = b_ih[n + 0] + b_hh[n + 0];
    float by_ = b_ih[n + 1] + b_hh[n + 1];
    float bz = b_ih[n + 2] + b_hh[n + 2];
    float bw = b_ih[n + 3] + b_hh[n + 3];
#pragma unroll
    for (int i = 0; i < 4; i++) {
        int b = ty * 4 + i;
        float4 v = make_float4(acc[i][0] + bx, acc[i][1] + by_,
                               acc[i][2] + bz, acc[i][3] + bw);
        *(float4*)(g_xg + ((size_t)t * B_ + b) * G_ + n) = v;
    }
}

__device__ __forceinline__ float sigf(float x) { return 1.f / (1.f + __expf(-x)); }

// ---------------- Phase B: persistent recurrence kernel ----------------
// Grid = 128 blocks (all resident), 256 threads. Block bx owns 8 hidden units
// j0=8*bx. W slice (32 gate-rows x [hi|lo]) lives in SMEM for all 512 steps.
// Per step: D[128][32] = [h_hi;h_lo] @ W^T over 2 passes; gates = D[b]+D[b+64].
// SMEM: W 32 tiles x 4KB = 128KB, A stage buffer 32KB, ssum 8.4KB.
static constexpr uint32_t OFF_W = 0;
static constexpr uint32_t OFF_A = 131072;
static constexpr uint32_t OFF_S = 131072 + 32768;
static constexpr uint32_t SMEM_USED = OFF_S + 64 * 33 * 4;
static constexpr uint32_t SMEM_REQ = SMEM_USED + 1024;

__global__ __launch_bounds__(256, 1) void lstm_persistent(
    const int* __restrict__ seq_len, float* __restrict__ out)
{
    extern __shared__ char dsm_raw[];
    uint32_t raw = smem_to_u32(dsm_raw);
    uint32_t sbase = (raw + 1023u) & ~1023u;
    char* sm = dsm_raw + (sbase - raw);

    int tid = threadIdx.x;
    int wid = tid >> 5, lane = tid & 31;
    int g = lane >> 2, tg = lane & 3;
    int bx = blockIdx.x;
    int j0 = bx * 8;
    int m0 = wid * 16;

    // ---- preload W slice into SMEM (once) ----
    {
        int lr = tid >> 3;              // 0..31
        int e8b = (tid & 7) * 8;        // 0..56
        int gn = (lr >> 3) * H_ + j0 + (lr & 7);
        const __nv_bfloat16* wrow = g_WW + (size_t)gn * 2048;
#pragma unroll
        for (int st = 0; st < 8; st++)
#pragma unroll
            for (int p = 0; p < 2; p++)
#pragma unroll
                for (int c = 0; c < 2; c++) {
                    uint4 v = *(const uint4*)(wrow + p * 1024 + st * 128 + c * 64 + e8b);
                    *(uint4*)(sm + OFF_W + (uint32_t)((st * 4 + p * 2 + c) * 4096)
                              + SWZ((uint32_t)(lr * 128 + e8b * 2))) = v;
                }
    }

    // loader indices for A stages
    int srow = tid >> 4;            // 0..15
    int e8   = (tid & 15) * 8;      // 0..120
    int ec   = e8 >> 6;
    uint32_t ekw = (uint32_t)((e8 & 63) * 2);

    // ldmatrix lane addressing
    int q = lane >> 3, r8 = lane & 7;
    uint32_t a_row = (uint32_t)(m0 + r8 + (q & 1) * 8);
    uint32_t a_kb  = (uint32_t)((q >> 1) * 16);
    uint32_t b_rowq = (uint32_t)(r8 + (q >> 1) * 8);
    uint32_t b_kb  = (uint32_t)((q & 1) * 16);

    // epilogue constants
    int sl0 = 0, sl1 = 0;
    if (wid < 4) {
        sl0 = seq_len[wid * 16 + g];
        sl1 = seq_len[wid * 16 + g + 8];
    }

    float* ssum = (float*)(sm + OFF_S);
    volatile int* flags = (volatile int*)g_flags;

    __syncthreads();

#pragma unroll 1
    for (int t = 0; t < T_; t++) {
        const __nv_bfloat16* __restrict__ hin = g_hh[t & 1];
        __nv_bfloat16* __restrict__ hout = g_hh[(t + 1) & 1];

        // prefetch xg for epilogue (independent, long latency to hide)
        float2 xr[2][4];
        if (wid < 4) {
#pragma unroll
            for (int rs = 0; rs < 2; rs++) {
                int b = wid * 16 + g + rs * 8;
                const float* xgb = g_xg + ((size_t)t * B_ + b) * G_ + j0 + tg * 2;
#pragma unroll
                for (int gate = 0; gate < 4; gate++)
                    xr[rs][gate] = *(const float2*)(xgb + gate * H_);
            }
        }

        // prefetch A stage 0
        uint4 va[8];
#pragma unroll
        for (int i = 0; i < 8; i++)
            va[i] = *(const uint4*)(hin + (size_t)(srow + i * 16) * H_ + e8);

        float acc[4][4] = {};

#pragma unroll
        for (int st = 0; st < 8; st++) {
            __syncthreads();      // previous stage's compute done (A buffer free)
#pragma unroll
            for (int i = 0; i < 8; i++) {
                int row = srow + i * 16;
                *(uint4*)(sm + OFF_A + ec * 16384 + SWZ((uint32_t)(row * 128) + ekw)) = va[i];
            }
            __syncthreads();
            if (st < 7) {
                int kc = (st + 1) * 128;
#pragma unroll
                for (int i = 0; i < 8; i++)
                    va[i] = *(const uint4*)(hin + (size_t)(srow + i * 16) * H_ + kc + e8);
            }
#pragma unroll
            for (int c = 0; c < 2; c++) {
#pragma unroll
                for (int kk = 0; kk < 4; kk++) {
                    uint32_t a0, a1, a2, a3;
                    ldsm_x4(a0, a1, a2, a3,
                            sbase + OFF_A + c * 16384 +
                            SWZ(a_row * 128 + (uint32_t)(kk * 32) + a_kb));
#pragma unroll
                    for (int p = 0; p < 2; p++) {
#pragma unroll
                        for (int tp = 0; tp < 2; tp++) {
                            uint32_t b0, b1, b2, b3;
                            ldsm_x4(b0, b1, b2, b3,
                                    sbase + OFF_W + (uint32_t)((st * 4 + p * 2 + c) * 4096) +
                                    SWZ((b_rowq + tp * 16) * 128 + (uint32_t)(kk * 32) + b_kb));
                            hmma16816(acc[tp * 2 + 0], a0, a1, a2, a3, b0, b1);
                            hmma16816(acc[tp * 2 + 1], a0, a1, a2, a3, b2, b3);
                        }
                    }
                }
            }
        }

        // ---- epilogue: gates[b][n] = D[b][n] + D[b+64][n] ----
        if (wid >= 4) {
            int b0r = (wid - 4) * 16 + g;
#pragma unroll
            for (int nt = 0; nt < 4; nt++) {
                int n = nt * 8 + tg * 2;
                ssum[b0r * 33 + n]           = acc[nt][0];
                ssum[b0r * 33 + n + 1]       = acc[nt][1];
                ssum[(b0r + 8) * 33 + n]     = acc[nt][2];
                ssum[(b0r + 8) * 33 + n + 1] = acc[nt][3];
            }
        }
        __syncthreads();

        if (wid < 4) {
#pragma unroll
            for (int rs = 0; rs < 2; rs++) {
                int b = wid * 16 + g + rs * 8;
                bool m = t < (rs ? sl1 : sl0);
#pragma unroll
                for (int cs = 0; cs < 2; cs++) {
                    int u = tg * 2 + cs;
                    int j = j0 + u;
                    float xb[4];
                    xb[0] = cs ? xr[rs][0].y : xr[rs][0].x;
                    xb[1] = cs ? xr[rs][1].y : xr[rs][1].x;
                    xb[2] = cs ? xr[rs][2].y : xr[rs][2].x;
                    xb[3] = cs ? xr[rs][3].y : xr[rs][3].x;
                    float xi = acc[0][rs * 2 + cs] + ssum[b * 33 + 0 * 8 + u] + xb[0];
                    float xf = acc[1][rs * 2 + cs] + ssum[b * 33 + 1 * 8 + u] + xb[1];
                    float xg = acc[2][rs * 2 + cs] + ssum[b * 33 + 2 * 8 + u] + xb[2];
                    float xo = acc[3][rs * 2 + cs] + ssum[b * 33 + 3 * 8 + u] + xb[3];
                    float si = sigf(xi), sf = sigf(xf), tgh = tanhf(xg), so = sigf(xo);
                    float cold = g_c[b * H_ + j];
                    float cn = fmaf(sf, cold, si * tgh);
                    float hn = so * tanhf(cn);
                    g_c[b * H_ + j] = cn;
                    __nv_bfloat16 hi = __float2bfloat16(hn);
                    hout[b * H_ + j] = hi;
                    hout[(size_t)(b + 64) * H_ + j] = __float2bfloat16(hn - __bfloat162float(hi));
                    out[((size_t)b * T_ + t) * H_ + j] = m ? hn : 0.f;
                }
            }
        }

        // ---- grid barrier: release then wait ----
        __threadfence();
        __syncthreads();
        if (tid == 0) flags[bx] = t + 1;
        if (tid < 128) {
            while (flags[tid] < t + 1) { }
        }
        __threadfence();
        __syncthreads();
    }
}

extern "C" void kernel_launch(void* const* d_in, const int* in_sizes, int n_in,
                              void* d_out, int out_size)
{
    const float* feature = (const float*)d_in[0];
    const float* W_ih    = (const float*)d_in[1];
    const float* W_hh    = (const float*)d_in[2];
    const float* b_ih    = (const float*)d_in[3];
    const float* b_hh    = (const float*)d_in[4];
    const int*   seq_len = (const int*)d_in[5];
    float* out = (float*)d_out;

    cudaFuncSetAttribute(lstm_persistent, cudaFuncAttributeMaxDynamicSharedMemorySize,
                         SMEM_REQ);

    init_state_kernel<<<(128 * H_ + 255) / 256, 256>>>();
    build_WW_kernel<<<(G_ * H_ + 255) / 256, 256>>>(W_hh);
    gemm_xg_kernel<<<dim3(G_ / 64, T_), 256>>>(feature, W_ih, b_ih, b_hh);
    lstm_persistent<<<128, 256, SMEM_REQ>>>(seq_len, out);
}

// round 6
// speedup vs baseline: 1.1620x; 1.1620x over previous
#include <cuda_runtime.h>
#include <cuda_bf16.h>
#include <math.h>
#include <stdint.h>

#define B_ 64
#define T_ 512
#define D_ 1024
#define H_ 1024
#define G_ 4096

// ---------------- device scratch (allocation-free rule) ----------------
__device__ float g_xg[(size_t)T_ * B_ * G_];            // [T][B][4H] pre-activations
__device__ __nv_bfloat16 g_hh[2][128 * H_];             // ping-pong; rows 0-63 h_hi, 64-127 h_lo
__device__ __nv_bfloat16 g_WW[(size_t)G_ * 2 * H_];     // [4096][2048]: 0-1023 W_hi, 1024-2047 W_lo
__device__ unsigned g_arrive;                           // grid barrier arrivals (monotonic)
__device__ volatile unsigned g_epoch;                   // grid barrier epoch

#define SWZ(off) ((off) ^ (((off) >> 3) & 0x70))

__device__ __forceinline__ uint32_t smem_to_u32(const void* p) {
    uint32_t a;
    asm("{ .reg .u64 t; cvta.to.shared.u64 t, %1; cvt.u32.u64 %0, t; }" : "=r"(a) : "l"(p));
    return a;
}

__device__ __forceinline__ void ldsm_x4(uint32_t& r0, uint32_t& r1, uint32_t& r2,
                                        uint32_t& r3, uint32_t addr) {
    asm volatile("ldmatrix.sync.aligned.m8n8.x4.shared.b16 {%0,%1,%2,%3}, [%4];"
                 : "=r"(r0), "=r"(r1), "=r"(r2), "=r"(r3) : "r"(addr));
}

__device__ __forceinline__ void hmma16816(float* d, uint32_t a0, uint32_t a1,
                                          uint32_t a2, uint32_t a3,
                                          uint32_t b0, uint32_t b1) {
    asm volatile(
        "mma.sync.aligned.m16n8k16.row.col.f32.bf16.bf16.f32 "
        "{%0,%1,%2,%3}, {%4,%5,%6,%7}, {%8,%9}, {%0,%1,%2,%3};"
        : "+f"(d[0]), "+f"(d[1]), "+f"(d[2]), "+f"(d[3])
        : "r"(a0), "r"(a1), "r"(a2), "r"(a3), "r"(b0), "r"(b1));
}

__device__ __forceinline__ float sigf(float x) {
    return __fdividef(1.f, 1.f + __expf(-x));
}
__device__ __forceinline__ float tanh_fast(float x) {
    x = fminf(fmaxf(x, -15.f), 15.f);
    float e = __expf(2.f * x);
    return __fdividef(e - 1.f, e + 1.f);
}

// ---------------- init kernels ----------------
__global__ void init_state_kernel() {
    int i = blockIdx.x * blockDim.x + threadIdx.x;
    if (i < 128 * H_) {
        g_hh[0][i] = __float2bfloat16(0.f);
    }
    if (i == 0) { g_arrive = 0; g_epoch = 0; }
}

__global__ void build_WW_kernel(const float* __restrict__ W_hh) {
    int i = blockIdx.x * blockDim.x + threadIdx.x;
    if (i < G_ * H_) {
        int row = i >> 10, col = i & 1023;
        float w = W_hh[i];
        __nv_bfloat16 hi = __float2bfloat16(w);
        __nv_bfloat16 lo = __float2bfloat16(w - __bfloat162float(hi));
        g_WW[(size_t)row * 2048 + col] = hi;
        g_WW[(size_t)row * 2048 + 1024 + col] = lo;
    }
}

// ---------------- Phase A: x_gates GEMM (fp32, proven) ----------------
__global__ __launch_bounds__(256) void gemm_xg_kernel(
    const float* __restrict__ feature, const float* __restrict__ W_ih,
    const float* __restrict__ b_ih, const float* __restrict__ b_hh)
{
    __shared__ __align__(16) float As[16][68];
    __shared__ __align__(16) float Bs[16][68];
    int tid = threadIdx.x;
    int tx = tid & 15, ty = tid >> 4;
    int n0 = blockIdx.x * 64;
    int t  = blockIdx.y;
    int lr = tid >> 2;
    int lk = (tid & 3) * 4;

    const float* fptr = feature + ((size_t)lr * T_ + t) * D_ + lk;
    const float* wptr = W_ih + (size_t)(n0 + lr) * D_ + lk;

    float acc[4][4] = {};
    for (int k0 = 0; k0 < D_; k0 += 16) {
        float4 av = *(const float4*)(fptr + k0);
        float4 bv = *(const float4*)(wptr + k0);
        __syncthreads();
        As[lk + 0][lr] = av.x; As[lk + 1][lr] = av.y;
        As[lk + 2][lr] = av.z; As[lk + 3][lr] = av.w;
        Bs[lk + 0][lr] = bv.x; Bs[lk + 1][lr] = bv.y;
        Bs[lk + 2][lr] = bv.z; Bs[lk + 3][lr] = bv.w;
        __syncthreads();
#pragma unroll
        for (int k = 0; k < 16; k++) {
            float4 a4 = *(const float4*)&As[k][ty * 4];
            float4 b4 = *(const float4*)&Bs[k][tx * 4];
            acc[0][0] = fmaf(a4.x, b4.x, acc[0][0]);
            acc[0][1] = fmaf(a4.x, b4.y, acc[0][1]);
            acc[0][2] = fmaf(a4.x, b4.z, acc[0][2]);
            acc[0][3] = fmaf(a4.x, b4.w, acc[0][3]);
            acc[1][0] = fmaf(a4.y, b4.x, acc[1][0]);
            acc[1][1] = fmaf(a4.y, b4.y, acc[1][1]);
            acc[1][2] = fmaf(a4.y, b4.z, acc[1][2]);
            acc[1][3] = fmaf(a4.y, b4.w, acc[1][3]);
            acc[2][0] = fmaf(a4.z, b4.x, acc[2][0]);
            acc[2][1] = fmaf(a4.z, b4.y, acc[2][1]);
            acc[2][2] = fmaf(a4.z, b4.z, acc[2][2]);
            acc[2][3] = fmaf(a4.z, b4.w, acc[2][3]);
            acc[3][0] = fmaf(a4.w, b4.x, acc[3][0]);
            acc[3][1] = fmaf(a4.w, b4.y, acc[3][1]);
            acc[3][2] = fmaf(a4.w, b4.z, acc[3][2]);
            acc[3][3] = fmaf(a4.w, b4.w, acc[3][3]);
        }
    }
    int n = n0 + tx * 4;
    float bx = b_ih[n + 0] + b_hh[n + 0];
    float by_ = b_ih[n + 1] + b_hh[n + 1];
    float bz = b_ih[n + 2] + b_hh[n + 2];
    float bw = b_ih[n + 3] + b_hh[n + 3];
#pragma unroll
    for (int i = 0; i < 4; i++) {
        int b = ty * 4 + i;
        float4 v = make_float4(acc[i][0] + bx, acc[i][1] + by_,
                               acc[i][2] + bz, acc[i][3] + bw);
        *(float4*)(g_xg + ((size_t)t * B_ + b) * G_ + n) = v;
    }
}

// ---------------- Phase B: persistent recurrence, 512 threads ----------------
// Grid = 128 blocks (all resident). Block bx owns 8 hidden units j0=8*bx.
// 16 warps: warp w -> pass p=w&1 (W_hi / W_lo), row-group rg=w>>1 (16 of 128 rows).
// Partial sums merged via smem ssum[2][128][33]; epilogue 1 item/thread.
static constexpr uint32_t OFF_W = 0;                    // 32 tiles x 4KB = 128KB
static constexpr uint32_t OFF_A = 131072;               // 32KB A stage (2 subtiles)
static constexpr uint32_t OFF_S = 131072 + 32768;       // ssum [2][128][33] f32 = 33792B
static constexpr uint32_t SMEM_USED = OFF_S + 2 * 128 * 33 * 4;
static constexpr uint32_t SMEM_REQ = SMEM_USED + 1024;

__global__ __launch_bounds__(512, 1) void lstm_persistent(
    const int* __restrict__ seq_len, float* __restrict__ out)
{
    extern __shared__ char dsm_raw[];
    uint32_t raw = smem_to_u32(dsm_raw);
    uint32_t sbase = (raw + 1023u) & ~1023u;
    char* sm = dsm_raw + (sbase - raw);

    int tid = threadIdx.x;
    int wid = tid >> 5, lane = tid & 31;
    int bx = blockIdx.x;
    int j0 = bx * 8;
    int p  = wid & 1;           // pass (W_hi / W_lo)
    int rg = wid >> 1;          // row group (16 rows)
    int m0 = rg * 16;

    // ---- preload W slice into SMEM (once): 32 tiles of 32 rows x 64 els ----
    {
        int lr = (tid >> 3) & 31;         // 0..31
        int e8b = (tid & 7) * 8;          // 0..56
        int half = tid >> 8;              // 0/1 -> tiles 0-15 / 16-31
        int gn = (lr >> 3) * H_ + j0 + (lr & 7);
        const __nv_bfloat16* wrow = g_WW + (size_t)gn * 2048;
#pragma unroll
        for (int k = 0; k < 16; k++) {
            int q = half * 16 + k;        // tile id = st*4 + pp*2 + c
            int st = q >> 2, pp = (q >> 1) & 1, c = q & 1;
            uint4 v = *(const uint4*)(wrow + pp * 1024 + st * 128 + c * 64 + e8b);
            *(uint4*)(sm + OFF_W + (uint32_t)(q * 4096)
                      + SWZ((uint32_t)(lr * 128 + e8b * 2))) = v;
        }
    }

    // A staging indices: 512 threads, 4 x uint4 each per stage
    int srow = tid >> 4;                  // 0..31
    int e8   = (tid & 15) * 8;            // 0..120
    int ec   = e8 >> 6;
    uint32_t ekw = (uint32_t)((e8 & 63) * 2);

    // ldmatrix lane addressing
    int q8 = lane >> 3, r8 = lane & 7;
    uint32_t a_row = (uint32_t)(m0 + r8 + (q8 & 1) * 8);
    uint32_t a_kb  = (uint32_t)((q8 >> 1) * 16);
    uint32_t b_rowq = (uint32_t)(r8 + (q8 >> 1) * 8);
    uint32_t b_kb  = (uint32_t)((q8 & 1) * 16);

    // epilogue item: thread owns (b, u) forever
    int eb = tid >> 3, eu = tid & 7;
    int ej = j0 + eu;
    int sl = seq_len[eb];
    float c_reg = 0.f;

    float* ssum = (float*)(sm + OFF_S);

    __syncthreads();

#pragma unroll 1
    for (int t = 0; t < T_; t++) {
        const __nv_bfloat16* __restrict__ hin = g_hh[t & 1];
        __nv_bfloat16* __restrict__ hout = g_hh[(t + 1) & 1];

        // prefetch xg for epilogue
        float xr[4];
        {
            const float* xgb = g_xg + ((size_t)t * B_ + eb) * G_ + ej;
#pragma unroll
            for (int gate = 0; gate < 4; gate++) xr[gate] = xgb[gate * H_];
        }

        // prefetch A stage 0
        uint4 va[4];
#pragma unroll
        for (int i = 0; i < 4; i++)
            va[i] = *(const uint4*)(hin + (size_t)(srow + i * 32) * H_ + e8);

        float acc[4][4] = {};

#pragma unroll
        for (int st = 0; st < 8; st++) {
            __syncthreads();      // A buffer free (prev stage consumed)
#pragma unroll
            for (int i = 0; i < 4; i++) {
                int row = srow + i * 32;
                *(uint4*)(sm + OFF_A + ec * 16384 + SWZ((uint32_t)(row * 128) + ekw)) = va[i];
            }
            __syncthreads();
            if (st < 7) {
                int kc = (st + 1) * 128;
#pragma unroll
                for (int i = 0; i < 4; i++)
                    va[i] = *(const uint4*)(hin + (size_t)(srow + i * 32) * H_ + kc + e8);
            }
#pragma unroll
            for (int c = 0; c < 2; c++) {
                uint32_t wtile = OFF_W + (uint32_t)((st * 4 + p * 2 + c) * 4096);
#pragma unroll
                for (int kk = 0; kk < 4; kk++) {
                    uint32_t a0, a1, a2, a3;
                    ldsm_x4(a0, a1, a2, a3,
                            sbase + OFF_A + c * 16384 +
                            SWZ(a_row * 128 + (uint32_t)(kk * 32) + a_kb));
#pragma unroll
                    for (int tp = 0; tp < 2; tp++) {
                        uint32_t b0, b1, b2, b3;
                        ldsm_x4(b0, b1, b2, b3,
                                sbase + wtile +
                                SWZ((b_rowq + tp * 16) * 128 + (uint32_t)(kk * 32) + b_kb));
                        hmma16816(acc[tp * 2 + 0], a0, a1, a2, a3, b0, b1);
                        hmma16816(acc[tp * 2 + 1], a0, a1, a2, a3, b2, b3);
                    }
                }
            }
        }

        // ---- merge partials via smem ----
        {
            int g = lane >> 2, tg = lane & 3;
            int rw0 = p * 128 + m0 + g;
#pragma unroll
            for (int nt = 0; nt < 4; nt++) {
                int n = nt * 8 + tg * 2;
                ssum[rw0 * 33 + n]           = acc[nt][0];
                ssum[rw0 * 33 + n + 1]       = acc[nt][1];
                ssum[(rw0 + 8) * 33 + n]     = acc[nt][2];
                ssum[(rw0 + 8) * 33 + n + 1] = acc[nt][3];
            }
        }
        __syncthreads();

        // ---- epilogue: one (b,u) per thread ----
        {
            float gate[4];
#pragma unroll
            for (int g4 = 0; g4 < 4; g4++) {
                int n = g4 * 8 + eu;
                gate[g4] = ssum[(0 * 128 + eb) * 33 + n]
                         + ssum[(1 * 128 + eb) * 33 + n]
                         + ssum[(0 * 128 + eb + 64) * 33 + n]
                         + ssum[(1 * 128 + eb + 64) * 33 + n]
                         + xr[g4];
            }
            float si = sigf(gate[0]);
            float sf = sigf(gate[1]);
            float tg = tanh_fast(gate[2]);
            float so = sigf(gate[3]);
            c_reg = fmaf(sf, c_reg, si * tg);
            float hn = so * tanh_fast(c_reg);
            __nv_bfloat16 hi = __float2bfloat16(hn);
            hout[eb * H_ + ej] = hi;
            hout[(size_t)(eb + 64) * H_ + ej] = __float2bfloat16(hn - __bfloat162float(hi));
            out[((size_t)eb * T_ + t) * H_ + ej] = (t < sl) ? hn : 0.f;
        }

        // ---- grid barrier ----
        __threadfence();
        __syncthreads();
        if (tid == 0) {
            unsigned v = atomicAdd(&g_arrive, 1u);
            if (v == 128u * (unsigned)(t + 1) - 1u) g_epoch = (unsigned)(t + 1);
            while (g_epoch < (unsigned)(t + 1)) { }
        }
        __syncthreads();
        __threadfence();
    }
}

extern "C" void kernel_launch(void* const* d_in, const int* in_sizes, int n_in,
                              void* d_out, int out_size)
{
    const float* feature = (const float*)d_in[0];
    const float* W_ih    = (const float*)d_in[1];
    const float* W_hh    = (const float*)d_in[2];
    const float* b_ih    = (const float*)d_in[3];
    const float* b_hh    = (const float*)d_in[4];
    const int*   seq_len = (const int*)d_in[5];
    float* out = (float*)d_out;

    cudaFuncSetAttribute(lstm_persistent, cudaFuncAttributeMaxDynamicSharedMemorySize,
                         SMEM_REQ);

    init_state_kernel<<<(128 * H_ + 255) / 256, 256>>>();
    build_WW_kernel<<<(G_ * H_ + 255) / 256, 256>>>(W_hh);
    gemm_xg_kernel<<<dim3(G_ / 64, T_), 256>>>(feature, W_ih, b_ih, b_hh);
    lstm_persistent<<<128, 512, SMEM_REQ>>>(seq_len, out);
}

// round 7
// speedup vs baseline: 1.3210x; 1.1368x over previous
#include <cuda_runtime.h>
#include <cuda_bf16.h>
#include <math.h>
#include <stdint.h>

#define B_ 64
#define T_ 512
#define D_ 1024
#define H_ 1024
#define G_ 4096

// ---------------- device scratch (allocation-free rule) ----------------
__device__ float g_xg[(size_t)T_ * B_ * G_];            // [T][B][4H] pre-activations
__device__ __nv_bfloat16 g_hh[2][128 * H_];             // ping-pong; rows 0-63 h_hi, 64-127 h_lo
__device__ __nv_bfloat16 g_WW[(size_t)G_ * 2 * H_];     // [4096][2048]: 0-1023 W_hi, 1024-2047 W_lo
__device__ unsigned g_arrive;                           // grid barrier arrivals (monotonic)
__device__ volatile unsigned g_epoch;                   // grid barrier epoch

#define SWZ(off) ((off) ^ (((off) >> 3) & 0x70))

__device__ __forceinline__ uint32_t smem_to_u32(const void* p) {
    uint32_t a;
    asm("{ .reg .u64 t; cvta.to.shared.u64 t, %1; cvt.u32.u64 %0, t; }" : "=r"(a) : "l"(p));
    return a;
}

__device__ __forceinline__ void ldsm_x4(uint32_t& r0, uint32_t& r1, uint32_t& r2,
                                        uint32_t& r3, uint32_t addr) {
    asm volatile("ldmatrix.sync.aligned.m8n8.x4.shared.b16 {%0,%1,%2,%3}, [%4];"
                 : "=r"(r0), "=r"(r1), "=r"(r2), "=r"(r3) : "r"(addr));
}

__device__ __forceinline__ void hmma16816(float* d, uint32_t a0, uint32_t a1,
                                          uint32_t a2, uint32_t a3,
                                          uint32_t b0, uint32_t b1) {
    asm volatile(
        "mma.sync.aligned.m16n8k16.row.col.f32.bf16.bf16.f32 "
        "{%0,%1,%2,%3}, {%4,%5,%6,%7}, {%8,%9}, {%0,%1,%2,%3};"
        : "+f"(d[0]), "+f"(d[1]), "+f"(d[2]), "+f"(d[3])
        : "r"(a0), "r"(a1), "r"(a2), "r"(a3), "r"(b0), "r"(b1));
}

__device__ __forceinline__ void cp_async16(uint32_t dst, const void* src) {
    asm volatile("cp.async.cg.shared.global [%0], [%1], 16;"
                 :: "r"(dst), "l"(src) : "memory");
}
#define CP_COMMIT() asm volatile("cp.async.commit_group;" ::: "memory")
#define CP_WAIT(N)  asm volatile("cp.async.wait_group %0;" :: "n"(N) : "memory")

__device__ __forceinline__ float sigf(float x) {
    return __fdividef(1.f, 1.f + __expf(-x));
}
__device__ __forceinline__ float tanh_fast(float x) {
    x = fminf(fmaxf(x, -15.f), 15.f);
    float e = __expf(2.f * x);
    return __fdividef(e - 1.f, e + 1.f);
}

// ---------------- init kernels ----------------
__global__ void init_state_kernel() {
    int i = blockIdx.x * blockDim.x + threadIdx.x;
    if (i < 128 * H_) g_hh[0][i] = __float2bfloat16(0.f);
    if (i == 0) { g_arrive = 0; g_epoch = 0; }
}

__global__ void build_WW_kernel(const float* __restrict__ W_hh) {
    int i = blockIdx.x * blockDim.x + threadIdx.x;
    if (i < G_ * H_) {
        int row = i >> 10, col = i & 1023;
        float w = W_hh[i];
        __nv_bfloat16 hi = __float2bfloat16(w);
        __nv_bfloat16 lo = __float2bfloat16(w - __bfloat162float(hi));
        g_WW[(size_t)row * 2048 + col] = hi;
        g_WW[(size_t)row * 2048 + 1024 + col] = lo;
    }
}

// ---------------- Phase A: x_gates GEMM (fp32, proven) ----------------
__global__ __launch_bounds__(256) void gemm_xg_kernel(
    const float* __restrict__ feature, const float* __restrict__ W_ih,
    const float* __restrict__ b_ih, const float* __restrict__ b_hh)
{
    __shared__ __align__(16) float As[16][68];
    __shared__ __align__(16) float Bs[16][68];
    int tid = threadIdx.x;
    int tx = tid & 15, ty = tid >> 4;
    int n0 = blockIdx.x * 64;
    int t  = blockIdx.y;
    int lr = tid >> 2;
    int lk = (tid & 3) * 4;

    const float* fptr = feature + ((size_t)lr * T_ + t) * D_ + lk;
    const float* wptr = W_ih + (size_t)(n0 + lr) * D_ + lk;

    float acc[4][4] = {};
    for (int k0 = 0; k0 < D_; k0 += 16) {
        float4 av = *(const float4*)(fptr + k0);
        float4 bv = *(const float4*)(wptr + k0);
        __syncthreads();
        As[lk + 0][lr] = av.x; As[lk + 1][lr] = av.y;
        As[lk + 2][lr] = av.z; As[lk + 3][lr] = av.w;
        Bs[lk + 0][lr] = bv.x; Bs[lk + 1][lr] = bv.y;
        Bs[lk + 2][lr] = bv.z; Bs[lk + 3][lr] = bv.w;
        __syncthreads();
#pragma unroll
        for (int k = 0; k < 16; k++) {
            float4 a4 = *(const float4*)&As[k][ty * 4];
            float4 b4 = *(const float4*)&Bs[k][tx * 4];
            acc[0][0] = fmaf(a4.x, b4.x, acc[0][0]);
            acc[0][1] = fmaf(a4.x, b4.y, acc[0][1]);
            acc[0][2] = fmaf(a4.x, b4.z, acc[0][2]);
            acc[0][3] = fmaf(a4.x, b4.w, acc[0][3]);
            acc[1][0] = fmaf(a4.y, b4.x, acc[1][0]);
            acc[1][1] = fmaf(a4.y, b4.y, acc[1][1]);
            acc[1][2] = fmaf(a4.y, b4.z, acc[1][2]);
            acc[1][3] = fmaf(a4.y, b4.w, acc[1][3]);
            acc[2][0] = fmaf(a4.z, b4.x, acc[2][0]);
            acc[2][1] = fmaf(a4.z, b4.y, acc[2][1]);
            acc[2][2] = fmaf(a4.z, b4.z, acc[2][2]);
            acc[2][3] = fmaf(a4.z, b4.w, acc[2][3]);
            acc[3][0] = fmaf(a4.w, b4.x, acc[3][0]);
            acc[3][1] = fmaf(a4.w, b4.y, acc[3][1]);
            acc[3][2] = fmaf(a4.w, b4.z, acc[3][2]);
            acc[3][3] = fmaf(a4.w, b4.w, acc[3][3]);
        }
    }
    int n = n0 + tx * 4;
    float bx = b_ih[n + 0] + b_hh[n + 0];
    float by_ = b_ih[n + 1] + b_hh[n + 1];
    float bz = b_ih[n + 2] + b_hh[n + 2];
    float bw = b_ih[n + 3] + b_hh[n + 3];
#pragma unroll
    for (int i = 0; i < 4; i++) {
        int b = ty * 4 + i;
        float4 v = make_float4(acc[i][0] + bx, acc[i][1] + by_,
                               acc[i][2] + bz, acc[i][3] + bw);
        *(float4*)(g_xg + ((size_t)t * B_ + b) * G_ + n) = v;
    }
}

// ---------------- Phase B: persistent recurrence, W in registers ----------------
// Grid = 128 blocks, 256 threads (8 warps). Block bx owns 8 hidden units.
// Warp w owns K-cols {s*256 + w*32 + kk*16} for stages s=0..3, kk=0..1,
// holding W fragments for BOTH passes in 128 registers (loaded once).
// Per step: acc[64][32] += h_hi@W_hi + h_hi@W_lo + h_lo@W_hi over its K-slice;
// partials (pre-reduced over hi/lo rows) merged via smem; epilogue 2 items/thread.
static constexpr uint32_t OFF_A0 = 0;                   // stage buf 0: 4 subtiles x 16KB
static constexpr uint32_t OFF_A1 = 65536;               // stage buf 1
static constexpr uint32_t OFF_S  = 131072;              // ssum [8][64][34] f32 = 69632B
static constexpr uint32_t SMEM_USED = OFF_S + 8 * 64 * 34 * 4;
static constexpr uint32_t SMEM_REQ  = SMEM_USED + 1024;

__global__ __launch_bounds__(256, 1) void lstm_persistent(
    const int* __restrict__ seq_len, float* __restrict__ out)
{
    extern __shared__ char dsm_raw[];
    uint32_t raw = smem_to_u32(dsm_raw);
    uint32_t sbase = (raw + 1023u) & ~1023u;
    char* sm = dsm_raw + (sbase - raw);

    int tid = threadIdx.x;
    int wid = tid >> 5, lane = tid & 31;
    int bx = blockIdx.x;
    int j0 = bx * 8;

    // ldmatrix lane addressing
    int q8 = lane >> 3, r8 = lane & 7;
    uint32_t a_lrow = (uint32_t)(r8 + (q8 & 1) * 8);     // + m-tile base
    uint32_t a_kb   = (uint32_t)((q8 >> 1) * 16);
    uint32_t b_lrow = (uint32_t)(r8 + (q8 >> 1) * 8);    // + nt2*16
    uint32_t b_kb   = (uint32_t)((q8 & 1) * 16);

    // ---- load W fragments into registers (once) ----
    uint32_t wr[4][2][2][4][2];
    {
        int rr = tid >> 3;                    // 0..31 (gate-row local)
        int cb = (tid & 7) * 8;               // 0..56
        int gn = (rr >> 3) * H_ + j0 + (rr & 7);
        const __nv_bfloat16* wrow = g_WW + (size_t)gn * 2048;
#pragma unroll
        for (int ch = 0; ch < 2; ch++) {      // pass: 0=hi, 1=lo
            __syncthreads();
            // stage 32 rows x 1024 cols into smem (16 subtiles x 4KB at OFF_A0)
#pragma unroll
            for (int it = 0; it < 16; it++) {
                uint4 v = *(const uint4*)(wrow + ch * 1024 + it * 64 + cb);
                *(uint4*)(sm + OFF_A0 + (uint32_t)(it * 4096)
                          + SWZ((uint32_t)(rr * 128 + cb * 2))) = v;
            }
            __syncthreads();
#pragma unroll
            for (int s = 0; s < 4; s++)
#pragma unroll
                for (int kk = 0; kk < 2; kk++) {
                    int scol = s * 256 + wid * 32 + kk * 16;
                    uint32_t sub = (uint32_t)(scol >> 6);
                    uint32_t cin2 = (uint32_t)((scol & 63) * 2);
#pragma unroll
                    for (int nt2 = 0; nt2 < 2; nt2++) {
                        uint32_t addr = sbase + OFF_A0 + sub * 4096 +
                            SWZ((nt2 * 16 + b_lrow) * 128 + cin2 + b_kb);
                        ldsm_x4(wr[s][kk][ch][nt2 * 2][0], wr[s][kk][ch][nt2 * 2][1],
                                wr[s][kk][ch][nt2 * 2 + 1][0], wr[s][kk][ch][nt2 * 2 + 1][1],
                                addr);
                    }
                }
        }
    }
    __syncthreads();

    // cp.async A-staging indices: thread covers colg (tid&31), rows (tid>>5)+8k
    int cg  = tid & 31;
    int rA0 = tid >> 5;
    int colEl = cg * 8;
    uint32_t a_dst_base = (uint32_t)((colEl >> 6) * 16384) +
                          (uint32_t)0;  // + SWZ(row*128 + (colEl&63)*2) per row
    uint32_t a_cin2 = (uint32_t)((colEl & 63) * 2);

    // epilogue: 2 items per thread
    int eb0 = tid >> 3, eu0 = tid & 7;
    int eb1 = (tid + 256) >> 3, eu1 = tid & 7;
    int sl0 = seq_len[eb0], sl1 = seq_len[eb1];
    float c0 = 0.f, c1 = 0.f;

    float* ssum = (float*)(sm + OFF_S);

#pragma unroll 1
    for (int t = 0; t < T_; t++) {
        const __nv_bfloat16* __restrict__ hin = g_hh[t & 1];
        __nv_bfloat16* __restrict__ hout = g_hh[(t + 1) & 1];

        // prefetch xg for epilogue
        float xr0[4], xr1[4];
        {
            const float* xa = g_xg + ((size_t)t * B_ + eb0) * G_ + j0 + eu0;
            const float* xb = g_xg + ((size_t)t * B_ + eb1) * G_ + j0 + eu1;
#pragma unroll
            for (int g4 = 0; g4 < 4; g4++) { xr0[g4] = xa[g4 * H_]; xr1[g4] = xb[g4 * H_]; }
        }

        // issue stage 0
        {
            const __nv_bfloat16* src = hin + (size_t)rA0 * H_ + colEl;
            uint32_t d0 = sbase + OFF_A0 + a_dst_base;
#pragma unroll
            for (int k = 0; k < 16; k++) {
                int row = rA0 + 8 * k;
                cp_async16(d0 + SWZ((uint32_t)(row * 128) + a_cin2),
                           src + (size_t)(8 * k) * H_);
            }
            CP_COMMIT();
        }

        float acc[4][4][4];
#pragma unroll
        for (int mt = 0; mt < 4; mt++)
#pragma unroll
            for (int nt = 0; nt < 4; nt++)
#pragma unroll
                for (int i = 0; i < 4; i++) acc[mt][nt][i] = 0.f;

#pragma unroll
        for (int s = 0; s < 4; s++) {
            uint32_t abuf = (s & 1) ? OFF_A1 : OFF_A0;
            if (s < 3) {
                uint32_t nbuf = (s & 1) ? OFF_A0 : OFF_A1;
                const __nv_bfloat16* src = hin + (size_t)rA0 * H_ + (s + 1) * 256 + colEl;
                uint32_t d0 = sbase + nbuf + a_dst_base;
#pragma unroll
                for (int k = 0; k < 16; k++) {
                    int row = rA0 + 8 * k;
                    cp_async16(d0 + SWZ((uint32_t)(row * 128) + a_cin2),
                               src + (size_t)(8 * k) * H_);
                }
                CP_COMMIT();
                CP_WAIT(1);
            } else {
                CP_WAIT(0);
            }
            __syncthreads();

#pragma unroll
            for (int kk = 0; kk < 2; kk++) {
                int scol = wid * 32 + kk * 16;           // col within stage
                uint32_t sub = (uint32_t)(scol >> 6);
                uint32_t cin2 = (uint32_t)((scol & 63) * 2) + a_kb;
                uint32_t atile = sbase + abuf + sub * 16384;
                // hi rows (0-63): both passes
                uint32_t ah[4][4];
#pragma unroll
                for (int mt = 0; mt < 4; mt++)
                    ldsm_x4(ah[mt][0], ah[mt][1], ah[mt][2], ah[mt][3],
                            atile + SWZ((mt * 16 + a_lrow) * 128 + cin2));
#pragma unroll
                for (int p = 0; p < 2; p++)
#pragma unroll
                    for (int mt = 0; mt < 4; mt++)
#pragma unroll
                        for (int nt = 0; nt < 4; nt++)
                            hmma16816(acc[mt][nt], ah[mt][0], ah[mt][1], ah[mt][2], ah[mt][3],
                                      wr[s][kk][p][nt][0], wr[s][kk][p][nt][1]);
                // lo rows (64-127): hi pass only (lo*lo dropped)
#pragma unroll
                for (int mt = 0; mt < 4; mt++)
                    ldsm_x4(ah[mt][0], ah[mt][1], ah[mt][2], ah[mt][3],
                            atile + SWZ((64 + mt * 16 + a_lrow) * 128 + cin2));
#pragma unroll
                for (int mt = 0; mt < 4; mt++)
#pragma unroll
                    for (int nt = 0; nt < 4; nt++)
                        hmma16816(acc[mt][nt], ah[mt][0], ah[mt][1], ah[mt][2], ah[mt][3],
                                  wr[s][kk][0][nt][0], wr[s][kk][0][nt][1]);
            }
            __syncthreads();
        }

        // ---- store pre-reduced partials ----
        {
            int r = lane >> 2, c4 = lane & 3;
            float* pp = ssum + wid * (64 * 34);
#pragma unroll
            for (int mt = 0; mt < 4; mt++)
#pragma unroll
                for (int nt = 0; nt < 4; nt++) {
                    int b1 = mt * 16 + r, n = nt * 8 + c4 * 2;
                    *(float2*)(pp + b1 * 34 + n) =
                        make_float2(acc[mt][nt][0], acc[mt][nt][1]);
                    *(float2*)(pp + (b1 + 8) * 34 + n) =
                        make_float2(acc[mt][nt][2], acc[mt][nt][3]);
                }
        }
        __syncthreads();

        // ---- epilogue: 2 items/thread ----
#pragma unroll
        for (int it = 0; it < 2; it++) {
            int b = it ? eb1 : eb0;
            int u = it ? eu1 : eu0;
            int j = j0 + u;
            float gate[4];
#pragma unroll
            for (int g4 = 0; g4 < 4; g4++) {
                int n = g4 * 8 + u;
                float s0 = 0.f;
#pragma unroll
                for (int w = 0; w < 8; w++)
                    s0 += ssum[w * (64 * 34) + b * 34 + n];
                gate[g4] = s0 + (it ? xr1[g4] : xr0[g4]);
            }
            float si = sigf(gate[0]);
            float sf = sigf(gate[1]);
            float tg = tanh_fast(gate[2]);
            float so = sigf(gate[3]);
            float cn = fmaf(sf, it ? c1 : c0, si * tg);
            if (it) c1 = cn; else c0 = cn;
            float hn = so * tanh_fast(cn);
            __nv_bfloat16 hi = __float2bfloat16(hn);
            hout[b * H_ + j] = hi;
            hout[(size_t)(b + 64) * H_ + j] = __float2bfloat16(hn - __bfloat162float(hi));
            out[((size_t)b * T_ + t) * H_ + j] = (t < (it ? sl1 : sl0)) ? hn : 0.f;
        }

        // ---- grid barrier ----
        __threadfence();
        __syncthreads();
        if (tid == 0) {
            unsigned v = atomicAdd(&g_arrive, 1u);
            if (v == 128u * (unsigned)(t + 1) - 1u) g_epoch = (unsigned)(t + 1);
            while (g_epoch < (unsigned)(t + 1)) { }
        }
        __syncthreads();
        __threadfence();
    }
}

extern "C" void kernel_launch(void* const* d_in, const int* in_sizes, int n_in,
                              void* d_out, int out_size)
{
    const float* feature = (const float*)d_in[0];
    const float* W_ih    = (const float*)d_in[1];
    const float* W_hh    = (const float*)d_in[2];
    const float* b_ih    = (const float*)d_in[3];
    const float* b_hh    = (const float*)d_in[4];
    const int*   seq_len = (const int*)d_in[5];
    float* out = (float*)d_out;

    cudaFuncSetAttribute(lstm_persistent, cudaFuncAttributeMaxDynamicSharedMemorySize,
                         SMEM_REQ);

    init_state_kernel<<<(128 * H_ + 255) / 256, 256>>>();
    build_WW_kernel<<<(G_ * H_ + 255) / 256, 256>>>(W_hh);
    gemm_xg_kernel<<<dim3(G_ / 64, T_), 256>>>(feature, W_ih, b_ih, b_hh);
    lstm_persistent<<<128, 256, SMEM_REQ>>>(seq_len, out);
}